// round 12
// baseline (speedup 1.0000x reference)
#include <cuda_runtime.h>
#include <cstdint>
#include <cstddef>

// ---------------------------------------------------------------- constants
#define NB     128
#define NTOK   1369
#define DINOD  384
#define CLIPD  512
#define NH     8
#define HD     64
#define TN     24          // tokens per tile (small => 2 CTAs/SM)
#define NT2    29          // ceil(685/24)
#define HALF0  685         // tokens in half 0 (half 1 gets 684)
#define DPITCH 388         // dino tile row pitch (floats)
#define QPITCH 392         // qk row pitch
#define PSP    28          // p row pitch (28*4=112B = 16B-aligned rows)

// dynamic smem layout for k_main (float offsets)
#define OFF_DS   0
#define OFF_QK   (2*TN*DPITCH)            // 18624
#define OFF_LP   (OFF_QK + NH*QPITCH)     // 21760
#define OFF_PS   (OFF_LP + 12*NH*TN)      // 24064
#define OFF_MRUN (OFF_PS + NH*PSP)        // 24288
#define OFF_LRUN (OFF_MRUN + NH)
#define OFF_ALPH (OFF_LRUN + NH)
#define SMEM_FLOATS (OFF_ALPH + NH)
#define SMEM_BYTES  (SMEM_FLOATS * 4)     // 97248 B

// packed fp32x2 ops (Blackwell FFMA2 — only reachable via PTX)
#define FMAF2(d, a, b) \
    asm("fma.rn.f32x2 %0, %1, %2, %0;" : "+l"(d) : "l"(a), "l"(b))
#define MULF2(d, a, b) \
    asm("mul.rn.f32x2 %0, %1, %2;" : "=l"(d) : "l"(a), "l"(b))
#define PACKF2(r, lo, hi) \
    asm("mov.b64 %0, {%1, %2};" : "=l"(r) : "f"(lo), "f"(hi))
#define UNPACKF2(lo, hi, r) \
    asm("mov.b64 {%0, %1}, %2;" : "=f"(lo), "=f"(hi) : "l"(r))

// device scratch (no allocation APIs allowed)
__device__ float  g_qk[NB * NH * DINOD];
__device__ float  g_ctx[NB * 2 * NH * DINOD];      // per-half unnormalized ctx
__device__ float2 g_ml[NB * 2 * NH];               // per-half (m, l)

static __device__ __forceinline__ void cp16(float* sdst, const float* gsrc, bool valid) {
    uint32_t s = (uint32_t)__cvta_generic_to_shared(sdst);
    int sz = valid ? 16 : 0;     // sz=0 -> zero-fill destination
    asm volatile("cp.async.cg.shared.global [%0], [%1], 16, %2;\n"
                 :: "r"(s), "l"(gsrc), "r"(sz) : "memory");
}
static __device__ __forceinline__ void cpcommit() {
    asm volatile("cp.async.commit_group;\n" ::: "memory");
}

// ---------------------------------------------------------------------------
// Prep: per (b-group of 4, head) block
//   stage A (smem-staged GEMM): Q[bi,d] = clip[b,:] @ Wq[:, h*64+d] + bq
//   stage B: qk[b,h,j] = Q[bi,:] . Wk[j, h*64:] / (8*temperature)
// grid (32, 8), 384 threads.
// ---------------------------------------------------------------------------
__global__ void __launch_bounds__(384)
k_prep(const float* __restrict__ clip, const float* __restrict__ Wq,
       const float* __restrict__ bq, const float* __restrict__ Wk,
       const float* __restrict__ temp) {
    __shared__ float clips[4 * CLIPD];     // 8 KB
    __shared__ float Wqs[2 * 64 * HD];     // 32 KB double buffer
    __shared__ float Qs[4 * HD];
    const int t  = threadIdx.x;
    const int bg = blockIdx.x;          // 0..31
    const int h  = blockIdx.y;          // 0..7

    // issue chunk 0 of Wq (64 rows x 64 cols), then load clip rows
    #pragma unroll
    for (int i = t; i < 1024; i += 384) {
        int r = i >> 4, c4 = i & 15;
        cp16(&Wqs[r * HD + c4 * 4], Wq + (size_t)r * CLIPD + h * HD + c4 * 4, true);
    }
    cpcommit();
    for (int i = t; i < 4 * CLIPD; i += 384)
        clips[i] = clip[(bg * 4 + (i >> 9)) * CLIPD + (i & 511)];

    float q0 = 0.f, q1 = 0.f, q2 = 0.f, q3 = 0.f;
    const int bi = t >> 6, d = t & 63;            // valid for t < 256

    for (int kc = 0; kc < 8; ++kc) {
        if (kc + 1 < 8) {
            float* dst = &Wqs[((kc + 1) & 1) * 64 * HD];
            #pragma unroll
            for (int i = t; i < 1024; i += 384) {
                int r = i >> 4, c4 = i & 15;
                cp16(&dst[r * HD + c4 * 4],
                     Wq + (size_t)((kc + 1) * 64 + r) * CLIPD + h * HD + c4 * 4, true);
            }
            cpcommit();
            asm volatile("cp.async.wait_group 1;\n" ::: "memory");
        } else {
            asm volatile("cp.async.wait_group 0;\n" ::: "memory");
        }
        __syncthreads();
        if (t < 256) {
            const float* wb = &Wqs[(kc & 1) * 64 * HD];
            const float* cb = &clips[bi * CLIPD + kc * 64];
            #pragma unroll
            for (int k = 0; k < 64; k += 4) {
                q0 += cb[k]     * wb[(k)     * HD + d];
                q1 += cb[k + 1] * wb[(k + 1) * HD + d];
                q2 += cb[k + 2] * wb[(k + 2) * HD + d];
                q3 += cb[k + 3] * wb[(k + 3) * HD + d];
            }
        }
        __syncthreads();
    }
    if (t < 256) Qs[t] = q0 + q1 + q2 + q3 + bq[h * HD + d];
    __syncthreads();

    // stage B: thread j computes 4 b's, Wk rows from L2 (reused 4x)
    const float inv_scale = 1.0f / (8.0f * temp[0]);
    const int j = t;
    const float4* w4 = reinterpret_cast<const float4*>(Wk + (size_t)j * CLIPD + h * HD);
    const float4* q4 = reinterpret_cast<const float4*>(Qs);
    float a0 = 0.f, a1 = 0.f, a2 = 0.f, a3 = 0.f;
    #pragma unroll
    for (int i = 0; i < 16; ++i) {
        float4 w  = w4[i];
        float4 x0 = q4[i], x1 = q4[16 + i], x2 = q4[32 + i], x3 = q4[48 + i];
        a0 += w.x * x0.x + w.y * x0.y + w.z * x0.z + w.w * x0.w;
        a1 += w.x * x1.x + w.y * x1.y + w.z * x1.z + w.w * x1.w;
        a2 += w.x * x2.x + w.y * x2.y + w.z * x2.z + w.w * x2.w;
        a3 += w.x * x3.x + w.y * x3.y + w.z * x3.z + w.w * x3.w;
    }
    g_qk[((size_t)(bg * 4 + 0) * NH + h) * DINOD + j] = a0 * inv_scale;
    g_qk[((size_t)(bg * 4 + 1) * NH + h) * DINOD + j] = a1 * inv_scale;
    g_qk[((size_t)(bg * 4 + 2) * NH + h) * DINOD + j] = a2 * inv_scale;
    g_qk[((size_t)(bg * 4 + 3) * NH + h) * DINOD + j] = a3 * inv_scale;
}

// ---------------------------------------------------------------------------
// Main: flash attention over a half of N per CTA. grid = 256 (2 per b),
// 384 threads, 2 CTAs/SM.
// ---------------------------------------------------------------------------
static __device__ __forceinline__ void issue_tile(const float* __restrict__ dino,
                                                  int b, int nstart, int count,
                                                  int tile, float* dst, int t) {
    #pragma unroll
    for (int i = 0; i < 6; ++i) {
        int idx = t + i * 384;          // < 2304 = 24 rows * 96 float4
        int row = idx / 96;
        int c4  = idx % 96;
        int tok = tile * TN + row;
        bool valid = (tok < count);
        int n = nstart + (valid ? tok : (count - 1));     // clamp addr, zfill data
        const float* src = dino + ((size_t)b * NTOK + n) * DINOD + c4 * 4;
        cp16(dst + row * DPITCH + c4 * 4, src, valid);
    }
    cpcommit();
}

__global__ void __launch_bounds__(384, 2)
k_main(const float* __restrict__ dino) {
    extern __shared__ float sm[];
    const int bid  = blockIdx.x;
    const int b    = bid >> 1;
    const int half = bid & 1;
    const int nstart = half ? HALF0 : 0;
    const int count  = half ? (NTOK - HALF0) : HALF0;
    const int t = threadIdx.x;
    const int w = t >> 5, l = t & 31;

    float* ds   = sm + OFF_DS;
    float* qks  = sm + OFF_QK;
    float* Lp   = sm + OFF_LP;
    float* ps   = sm + OFF_PS;
    float* mrun = sm + OFF_MRUN;
    float* lrun = sm + OFF_LRUN;
    float* alph = sm + OFF_ALPH;

    for (int i = t; i < NH * DINOD; i += 384)
        qks[(i / DINOD) * QPITCH + (i % DINOD)] = g_qk[(size_t)b * NH * DINOD + i];
    if (t < NH) { mrun[t] = -3.0e38f; lrun[t] = 0.f; }

    unsigned long long ctx2[NH];
    #pragma unroll
    for (int h = 0; h < NH; ++h) ctx2[h] = 0ull;

    issue_tile(dino, b, nstart, count, 0, ds, t);

    // phase-2 decomposition: 8 n-groups (3 tokens) x 48 j-splits (8 j)
    const int gn = l & 7;
    const int gj = (w << 2) | (l >> 3);
    const int j0 = gj * 8;

    for (int tt = 0; tt < NT2; ++tt) {
        const float* dsb = ds + (tt & 1) * TN * DPITCH;
        if (tt + 1 < NT2) {
            issue_tile(dino, b, nstart, count, tt + 1,
                       ds + ((tt + 1) & 1) * TN * DPITCH, t);
            asm volatile("cp.async.wait_group 1;\n" ::: "memory");
        } else {
            asm volatile("cp.async.wait_group 0;\n" ::: "memory");
        }
        __syncthreads();

        // ---- phase 2: logits partials, 4-head groups (register budget)
        #pragma unroll
        for (int hg = 0; hg < 2; ++hg) {
            unsigned long long acc2[4][3];
            #pragma unroll
            for (int hh = 0; hh < 4; ++hh)
                #pragma unroll
                for (int k = 0; k < 3; ++k) acc2[hh][k] = 0ull;

            #pragma unroll
            for (int jj = 0; jj < 2; ++jj) {
                const int jc = j0 + jj * 4;
                ulonglong2 a2[4];
                #pragma unroll
                for (int hh = 0; hh < 4; ++hh)
                    a2[hh] = *reinterpret_cast<const ulonglong2*>(
                                 &qks[(hg * 4 + hh) * QPITCH + jc]);
                #pragma unroll
                for (int k = 0; k < 3; ++k) {
                    ulonglong2 d2 = *reinterpret_cast<const ulonglong2*>(
                                        &dsb[(gn * 3 + k) * DPITCH + jc]);
                    #pragma unroll
                    for (int hh = 0; hh < 4; ++hh) {
                        FMAF2(acc2[hh][k], a2[hh].x, d2.x);
                        FMAF2(acc2[hh][k], a2[hh].y, d2.y);
                    }
                }
            }
            #pragma unroll
            for (int hh = 0; hh < 4; ++hh)
                #pragma unroll
                for (int k = 0; k < 3; ++k) {
                    float lo, hi;
                    UNPACKF2(lo, hi, acc2[hh][k]);
                    float v = lo + hi;
                    v += __shfl_down_sync(0xffffffffu, v, 16);
                    v += __shfl_down_sync(0xffffffffu, v, 8);
                    if (l < 8)
                        Lp[(w * NH + hg * 4 + hh) * TN + gn * 3 + k] = v;
                }
        }
        __syncthreads();

        // ---- softmax: warp h owns head h (24 tokens)
        if (w < NH) {
            const int h = w;
            const int valid = min(TN, count - tt * TN);
            float v = -3.0e38f;
            if (l < valid) {
                float x = 0.f;
                #pragma unroll
                for (int s = 0; s < 12; ++s) x += Lp[(s * NH + h) * TN + l];
                v = x;
            }
            float m = v;
            #pragma unroll
            for (int o = 16; o > 0; o >>= 1)
                m = fmaxf(m, __shfl_xor_sync(0xffffffffu, m, o));
            float mold = mrun[h];
            float mnew = fmaxf(mold, m);
            float p = (l < valid) ? __expf(v - mnew) : 0.f;
            if (l < TN) ps[h * PSP + l] = p;
            float s = p;
            #pragma unroll
            for (int o = 16; o > 0; o >>= 1)
                s += __shfl_xor_sync(0xffffffffu, s, o);
            if (l == 0) {
                float al = __expf(mold - mnew);
                alph[h] = al;
                lrun[h] = lrun[h] * al + s;
                mrun[h] = mnew;
            }
        }
        __syncthreads();

        // ---- phase 3: rank-24 ctx update; thread owns column j = t
        #pragma unroll
        for (int h = 0; h < NH; ++h) {
            float al = alph[h];
            unsigned long long aa;
            PACKF2(aa, al, al);
            MULF2(ctx2[h], ctx2[h], aa);
        }
        #pragma unroll
        for (int n4 = 0; n4 < 6; ++n4) {
            float d0 = dsb[(n4 * 4 + 0) * DPITCH + t];
            float d1 = dsb[(n4 * 4 + 1) * DPITCH + t];
            float d2 = dsb[(n4 * 4 + 2) * DPITCH + t];
            float d3 = dsb[(n4 * 4 + 3) * DPITCH + t];
            unsigned long long dd01, dd23;
            PACKF2(dd01, d0, d1);
            PACKF2(dd23, d2, d3);
            #pragma unroll
            for (int hg = 0; hg < 2; ++hg) {
                ulonglong2 p2[4];
                #pragma unroll
                for (int hh = 0; hh < 4; ++hh)
                    p2[hh] = *reinterpret_cast<const ulonglong2*>(
                                 &ps[(hg * 4 + hh) * PSP + n4 * 4]);
                #pragma unroll
                for (int hh = 0; hh < 4; ++hh) {
                    FMAF2(ctx2[hg * 4 + hh], p2[hh].x, dd01);
                    FMAF2(ctx2[hg * 4 + hh], p2[hh].y, dd23);
                }
            }
        }
        __syncthreads();
    }

    // ---- write per-half results to scratch
    #pragma unroll
    for (int h = 0; h < NH; ++h) {
        float lo, hi;
        UNPACKF2(lo, hi, ctx2[h]);
        g_ctx[((size_t)bid * NH + h) * DINOD + t] = lo + hi;
    }
    if (t < NH)
        g_ml[bid * NH + t] = make_float2(mrun[t], lrun[t]);
}

// ---------------------------------------------------------------------------
// Finalize: combine halves + ctx@Wv + bv + LayerNorm. grid = 128, 384 thr.
// ---------------------------------------------------------------------------
__global__ void __launch_bounds__(384)
k_fin(const float* __restrict__ Wv, const float* __restrict__ bv,
      const float* __restrict__ gamma, const float* __restrict__ beta,
      float* __restrict__ out) {
    __shared__ float ctxs[NH * DPITCH];
    __shared__ float outs[CLIPD];
    __shared__ float red[12], red2[12], stat[2];
    const int b = blockIdx.x;
    const int t = threadIdx.x;
    const int w = t >> 5, l = t & 31;

    #pragma unroll
    for (int h = 0; h < NH; ++h) {
        float2 ml0 = g_ml[(b * 2 + 0) * NH + h];
        float2 ml1 = g_ml[(b * 2 + 1) * NH + h];
        float m  = fmaxf(ml0.x, ml1.x);
        float f0 = __expf(ml0.x - m);
        float f1 = __expf(ml1.x - m);
        float inv = 1.0f / (ml0.y * f0 + ml1.y * f1);
        float c0 = g_ctx[((size_t)(b * 2 + 0) * NH + h) * DINOD + t];
        float c1 = g_ctx[((size_t)(b * 2 + 1) * NH + h) * DINOD + t];
        ctxs[h * DPITCH + t] = (c0 * f0 + c1 * f1) * inv;
    }
    __syncthreads();

    for (int c = t; c < CLIPD; c += 384) {
        const int h = c >> 6;
        const float* crow = ctxs + h * DPITCH;
        const float* wcol = Wv + c;
        float a0 = 0.f, a1 = 0.f, a2 = 0.f, a3 = 0.f;
        float a4 = 0.f, a5 = 0.f, a6 = 0.f, a7 = 0.f;
        #pragma unroll 2
        for (int jx = 0; jx < DINOD; jx += 8) {
            a0 += crow[jx]     * wcol[(size_t)jx * CLIPD];
            a1 += crow[jx + 1] * wcol[(size_t)(jx + 1) * CLIPD];
            a2 += crow[jx + 2] * wcol[(size_t)(jx + 2) * CLIPD];
            a3 += crow[jx + 3] * wcol[(size_t)(jx + 3) * CLIPD];
            a4 += crow[jx + 4] * wcol[(size_t)(jx + 4) * CLIPD];
            a5 += crow[jx + 5] * wcol[(size_t)(jx + 5) * CLIPD];
            a6 += crow[jx + 6] * wcol[(size_t)(jx + 6) * CLIPD];
            a7 += crow[jx + 7] * wcol[(size_t)(jx + 7) * CLIPD];
        }
        outs[c] = a0 + a1 + a2 + a3 + a4 + a5 + a6 + a7 + bv[c];
    }
    __syncthreads();

    float s = 0.f, s2 = 0.f;
    for (int c = t; c < CLIPD; c += 384) { float v = outs[c]; s += v; s2 += v * v; }
    #pragma unroll
    for (int o = 16; o > 0; o >>= 1) {
        s  += __shfl_xor_sync(0xffffffffu, s, o);
        s2 += __shfl_xor_sync(0xffffffffu, s2, o);
    }
    if (l == 0) { red[w] = s; red2[w] = s2; }
    __syncthreads();
    if (t == 0) {
        float ss = 0.f, ss2 = 0.f;
        for (int i = 0; i < 12; ++i) { ss += red[i]; ss2 += red2[i]; }
        float mu  = ss / 512.f;
        float var = ss2 / 512.f - mu * mu;
        stat[0] = mu;
        stat[1] = rsqrtf(var + 1e-5f);
    }
    __syncthreads();
    float mu = stat[0], rs = stat[1];
    for (int c = t; c < CLIPD; c += 384)
        out[(size_t)b * CLIPD + c] = (outs[c] - mu) * rs * gamma[c] + beta[c];
}

// ---------------------------------------------------------------------------
extern "C" void kernel_launch(void* const* d_in, const int* in_sizes, int n_in,
                              void* d_out, int out_size) {
    const float* dino  = (const float*)d_in[0];
    const float* clip  = (const float*)d_in[1];
    const float* Wq    = (const float*)d_in[2];
    const float* bq    = (const float*)d_in[3];
    const float* Wk    = (const float*)d_in[4];
    // d_in[5] = bk: cancels in softmax (constant per (b,h))
    const float* Wv    = (const float*)d_in[6];
    const float* bv    = (const float*)d_in[7];
    const float* temp  = (const float*)d_in[8];
    const float* gamma = (const float*)d_in[9];
    const float* beta  = (const float*)d_in[10];
    float* out = (float*)d_out;
    (void)in_sizes; (void)n_in; (void)out_size;

    cudaFuncSetAttribute(k_main, cudaFuncAttributeMaxDynamicSharedMemorySize, SMEM_BYTES);

    k_prep<<<dim3(32, 8), 384>>>(clip, Wq, bq, Wk, temp);
    k_main<<<NB * 2, 384, SMEM_BYTES>>>(dino);
    k_fin<<<NB, 384>>>(Wv, bv, gamma, beta, out);
}

// round 14
// speedup vs baseline: 1.3799x; 1.3799x over previous
#include <cuda_runtime.h>
#include <cstdint>
#include <cstddef>

// ---------------------------------------------------------------- constants
#define NB     128
#define NTOK   1369
#define DINOD  384
#define CLIPD  512
#define NH     8
#define HD     64
#define TN     48          // tokens per tile
#define NT     29          // ceil(1369/48)
#define DPITCH 388         // dino tile row pitch (floats): 16B-aligned, bank-skewed
#define QPITCH 392         // qk row pitch (16B-aligned)
#define PSP    52          // p row pitch (52*4=208 B, 16B-aligned)

// dynamic smem layout for k_main (float offsets)
#define OFF_DS   0
#define OFF_QK   (2*TN*DPITCH)            // 37248
#define OFF_LP   (OFF_QK + NH*QPITCH)     // 40384
#define OFF_PS   (OFF_LP + 12*NH*TN)      // 44992
#define OFF_OUTS (OFF_PS + NH*PSP)        // 45408
#define OFF_MRUN (OFF_OUTS + CLIPD)       // 45920
#define OFF_LRUN (OFF_MRUN + NH)
#define OFF_ALPH (OFF_LRUN + NH)
#define OFF_RED  (OFF_ALPH + NH)
#define OFF_RED2 (OFF_RED + 12)
#define OFF_STAT (OFF_RED2 + 12)
#define SMEM_FLOATS (OFF_STAT + 2)
#define SMEM_BYTES  (SMEM_FLOATS * 4)

// packed fp32x2 ops (Blackwell FFMA2 — only reachable via PTX)
#define FMAF2(d, a, b) \
    asm("fma.rn.f32x2 %0, %1, %2, %0;" : "+l"(d) : "l"(a), "l"(b))
#define MULF2(d, a, b) \
    asm("mul.rn.f32x2 %0, %1, %2;" : "=l"(d) : "l"(a), "l"(b))
#define PACKF2(r, lo, hi) \
    asm("mov.b64 %0, {%1, %2};" : "=l"(r) : "f"(lo), "f"(hi))
#define UNPACKF2(lo, hi, r) \
    asm("mov.b64 {%0, %1}, %2;" : "=f"(lo), "=f"(hi) : "l"(r))

// device scratch (no allocation APIs allowed)
__device__ float g_qk[NB * NH * DINOD];

static __device__ __forceinline__ void cp16(float* sdst, const float* gsrc, bool valid) {
    uint32_t s = (uint32_t)__cvta_generic_to_shared(sdst);
    int sz = valid ? 16 : 0;     // sz=0 -> zero-fill destination
    asm volatile("cp.async.cg.shared.global [%0], [%1], 16, %2;\n"
                 :: "r"(s), "l"(gsrc), "r"(sz) : "memory");
}
static __device__ __forceinline__ void cpcommit() {
    asm volatile("cp.async.commit_group;\n" ::: "memory");
}

// ---------------------------------------------------------------------------
// Prep (R12 version, 21.5us measured): per (b-group of 4, head) block
//   stage A (smem-staged GEMM): Q[bi,d] = clip[b,:] @ Wq[:, h*64+d] + bq
//   stage B: qk[b,h,j] = Q[bi,:] . Wk[j, h*64:] / (8*temperature)
// grid (32, 8), 384 threads.
// ---------------------------------------------------------------------------
__global__ void __launch_bounds__(384)
k_prep(const float* __restrict__ clip, const float* __restrict__ Wq,
       const float* __restrict__ bq, const float* __restrict__ Wk,
       const float* __restrict__ temp) {
    __shared__ float clips[4 * CLIPD];     // 8 KB
    __shared__ float Wqs[2 * 64 * HD];     // 32 KB double buffer
    __shared__ float Qs[4 * HD];
    const int t  = threadIdx.x;
    const int bg = blockIdx.x;          // 0..31
    const int h  = blockIdx.y;          // 0..7

    #pragma unroll
    for (int i = t; i < 1024; i += 384) {
        int r = i >> 4, c4 = i & 15;
        cp16(&Wqs[r * HD + c4 * 4], Wq + (size_t)r * CLIPD + h * HD + c4 * 4, true);
    }
    cpcommit();
    for (int i = t; i < 4 * CLIPD; i += 384)
        clips[i] = clip[(bg * 4 + (i >> 9)) * CLIPD + (i & 511)];

    float q0 = 0.f, q1 = 0.f, q2 = 0.f, q3 = 0.f;
    const int bi = t >> 6, d = t & 63;            // valid for t < 256

    for (int kc = 0; kc < 8; ++kc) {
        if (kc + 1 < 8) {
            float* dst = &Wqs[((kc + 1) & 1) * 64 * HD];
            #pragma unroll
            for (int i = t; i < 1024; i += 384) {
                int r = i >> 4, c4 = i & 15;
                cp16(&dst[r * HD + c4 * 4],
                     Wq + (size_t)((kc + 1) * 64 + r) * CLIPD + h * HD + c4 * 4, true);
            }
            cpcommit();
            asm volatile("cp.async.wait_group 1;\n" ::: "memory");
        } else {
            asm volatile("cp.async.wait_group 0;\n" ::: "memory");
        }
        __syncthreads();
        if (t < 256) {
            const float* wb = &Wqs[(kc & 1) * 64 * HD];
            const float* cb = &clips[bi * CLIPD + kc * 64];
            #pragma unroll
            for (int k = 0; k < 64; k += 4) {
                q0 += cb[k]     * wb[(k)     * HD + d];
                q1 += cb[k + 1] * wb[(k + 1) * HD + d];
                q2 += cb[k + 2] * wb[(k + 2) * HD + d];
                q3 += cb[k + 3] * wb[(k + 3) * HD + d];
            }
        }
        __syncthreads();
    }
    if (t < 256) Qs[t] = q0 + q1 + q2 + q3 + bq[h * HD + d];
    __syncthreads();

    const float inv_scale = 1.0f / (8.0f * temp[0]);
    const int j = t;
    const float4* w4 = reinterpret_cast<const float4*>(Wk + (size_t)j * CLIPD + h * HD);
    const float4* q4 = reinterpret_cast<const float4*>(Qs);
    float a0 = 0.f, a1 = 0.f, a2 = 0.f, a3 = 0.f;
    #pragma unroll
    for (int i = 0; i < 16; ++i) {
        float4 w  = w4[i];
        float4 x0 = q4[i], x1 = q4[16 + i], x2 = q4[32 + i], x3 = q4[48 + i];
        a0 += w.x * x0.x + w.y * x0.y + w.z * x0.z + w.w * x0.w;
        a1 += w.x * x1.x + w.y * x1.y + w.z * x1.z + w.w * x1.w;
        a2 += w.x * x2.x + w.y * x2.y + w.z * x2.z + w.w * x2.w;
        a3 += w.x * x3.x + w.y * x3.y + w.z * x3.z + w.w * x3.w;
    }
    g_qk[((size_t)(bg * 4 + 0) * NH + h) * DINOD + j] = a0 * inv_scale;
    g_qk[((size_t)(bg * 4 + 1) * NH + h) * DINOD + j] = a1 * inv_scale;
    g_qk[((size_t)(bg * 4 + 2) * NH + h) * DINOD + j] = a2 * inv_scale;
    g_qk[((size_t)(bg * 4 + 3) * NH + h) * DINOD + j] = a3 * inv_scale;
}

// ---------------------------------------------------------------------------
// Main (R10 version, 146.7us measured): per-b flash attention over N=1369,
// fused ctx@Wv + bv + LayerNorm epilogue. grid = 128, 384 threads, 144 regs.
// ---------------------------------------------------------------------------
static __device__ __forceinline__ void issue_tile(const float* __restrict__ dino,
                                                  int b, int tile, float* dst, int t) {
    const int n0 = tile * TN;
    #pragma unroll
    for (int i = 0; i < 12; ++i) {
        int idx = t + i * 384;          // < 4608 = 48 rows * 96 float4
        int row = idx / 96;
        int c4  = idx % 96;
        int n   = n0 + row;
        bool valid = (n < NTOK);
        int nc = valid ? n : (NTOK - 1);                  // clamp addr, zfill data
        const float* src = dino + ((size_t)b * NTOK + nc) * DINOD + c4 * 4;
        cp16(dst + row * DPITCH + c4 * 4, src, valid);
    }
    cpcommit();
}

__global__ void __launch_bounds__(384)
k_main(const float* __restrict__ dino, const float* __restrict__ Wv,
       const float* __restrict__ bv, const float* __restrict__ gamma,
       const float* __restrict__ beta, float* __restrict__ out) {
    extern __shared__ float sm[];
    const int b = blockIdx.x;
    const int t = threadIdx.x;
    const int w = t >> 5, l = t & 31;

    float* ds   = sm + OFF_DS;
    float* qks  = sm + OFF_QK;
    float* Lp   = sm + OFF_LP;
    float* ps   = sm + OFF_PS;
    float* outs = sm + OFF_OUTS;
    float* mrun = sm + OFF_MRUN;
    float* lrun = sm + OFF_LRUN;
    float* alph = sm + OFF_ALPH;
    float* red  = sm + OFF_RED;
    float* red2 = sm + OFF_RED2;
    float* stat = sm + OFF_STAT;

    for (int i = t; i < NH * DINOD; i += 384)
        qks[(i / DINOD) * QPITCH + (i % DINOD)] = g_qk[(size_t)b * NH * DINOD + i];
    if (t < NH) { mrun[t] = -3.0e38f; lrun[t] = 0.f; }

    unsigned long long ctx2[NH];
    #pragma unroll
    for (int h = 0; h < NH; ++h) ctx2[h] = 0ull;

    issue_tile(dino, b, 0, ds, t);

    // phase-2 decomposition: 16 n-groups (3 tokens) x 24 j-splits (16 j)
    const int gn = l & 15;
    const int gj = (w << 1) | (l >> 4);
    const int j0 = gj * 16;

    for (int tt = 0; tt < NT; ++tt) {
        const float* dsb = ds + (tt & 1) * TN * DPITCH;
        if (tt + 1 < NT) {
            issue_tile(dino, b, tt + 1, ds + ((tt + 1) & 1) * TN * DPITCH, t);
            asm volatile("cp.async.wait_group 1;\n" ::: "memory");
        } else {
            asm volatile("cp.async.wait_group 0;\n" ::: "memory");
        }
        __syncthreads();   // tile tt visible to all threads

        // ---- phase 2: logits partials C[8h][48n] over j-chunk of 16 (fp32x2)
        unsigned long long acc2[NH][3];
        #pragma unroll
        for (int h = 0; h < NH; ++h)
            #pragma unroll
            for (int k = 0; k < 3; ++k) acc2[h][k] = 0ull;

        #pragma unroll
        for (int jj = 0; jj < 4; ++jj) {
            const int jc = j0 + jj * 4;
            ulonglong2 a2[NH];
            #pragma unroll
            for (int h = 0; h < NH; ++h)
                a2[h] = *reinterpret_cast<const ulonglong2*>(&qks[h * QPITCH + jc]);
            #pragma unroll
            for (int k = 0; k < 3; ++k) {
                ulonglong2 d2 = *reinterpret_cast<const ulonglong2*>(&dsb[(gn * 3 + k) * DPITCH + jc]);
                #pragma unroll
                for (int h = 0; h < NH; ++h) {
                    FMAF2(acc2[h][k], a2[h].x, d2.x);
                    FMAF2(acc2[h][k], a2[h].y, d2.y);
                }
            }
        }
        #pragma unroll
        for (int h = 0; h < NH; ++h)
            #pragma unroll
            for (int k = 0; k < 3; ++k) {
                float lo, hi;
                UNPACKF2(lo, hi, acc2[h][k]);
                float v = lo + hi;
                v += __shfl_down_sync(0xffffffffu, v, 16);
                if (l < 16) Lp[(w * NH + h) * TN + gn * 3 + k] = v;
            }
        __syncthreads();

        // ---- softmax (warp h owns head h; reduces 12 partials itself)
        if (w < NH) {
            const int h = w;
            const int valid = (tt == NT - 1) ? (NTOK - (NT - 1) * TN) : TN;
            float v0 = 0.f;
            #pragma unroll
            for (int s = 0; s < 12; ++s) v0 += Lp[(s * NH + h) * TN + l];
            float v1 = -3.0e38f;
            if (l < 16) {
                float x = 0.f;
                #pragma unroll
                for (int s = 0; s < 12; ++s) x += Lp[(s * NH + h) * TN + l + 32];
                v1 = x;
            }
            if (l >= valid) v0 = -3.0e38f;
            if (l < 16 && l + 32 >= valid) v1 = -3.0e38f;

            float m = fmaxf(v0, v1);
            #pragma unroll
            for (int o = 16; o > 0; o >>= 1)
                m = fmaxf(m, __shfl_xor_sync(0xffffffffu, m, o));
            float mold = mrun[h];
            float mnew = fmaxf(mold, m);

            float p0 = (l < valid) ? __expf(v0 - mnew) : 0.f;
            float p1 = (l < 16 && l + 32 < valid) ? __expf(v1 - mnew) : 0.f;
            ps[h * PSP + l] = p0;
            if (l < 16) ps[h * PSP + l + 32] = p1;
            float s = p0 + p1;
            #pragma unroll
            for (int o = 16; o > 0; o >>= 1)
                s += __shfl_xor_sync(0xffffffffu, s, o);
            if (l == 0) {
                float al = __expf(mold - mnew);
                alph[h] = al;
                lrun[h] = lrun[h] * al + s;
                mrun[h] = mnew;
            }
        }
        __syncthreads();

        // ---- phase 3: rank-48 ctx update (fp32x2); thread owns column j = t
        #pragma unroll
        for (int h = 0; h < NH; ++h) {
            float al = alph[h];
            unsigned long long aa;
            PACKF2(aa, al, al);
            MULF2(ctx2[h], ctx2[h], aa);
        }
        #pragma unroll
        for (int n4 = 0; n4 < 12; ++n4) {
            ulonglong2 p2[NH];
            #pragma unroll
            for (int h = 0; h < NH; ++h)
                p2[h] = *reinterpret_cast<const ulonglong2*>(&ps[h * PSP + n4 * 4]);
            float d0 = dsb[(n4 * 4 + 0) * DPITCH + t];
            float d1 = dsb[(n4 * 4 + 1) * DPITCH + t];
            float d2 = dsb[(n4 * 4 + 2) * DPITCH + t];
            float d3 = dsb[(n4 * 4 + 3) * DPITCH + t];
            unsigned long long dd01, dd23;
            PACKF2(dd01, d0, d1);
            PACKF2(dd23, d2, d3);
            #pragma unroll
            for (int h = 0; h < NH; ++h) {
                FMAF2(ctx2[h], p2[h].x, dd01);
                FMAF2(ctx2[h], p2[h].y, dd23);
            }
        }
        __syncthreads();
    }

    // ---- epilogue: out = (ctx/l) @ Wv + bv, then LayerNorm
    #pragma unroll
    for (int h = 0; h < NH; ++h) {
        float lo, hi;
        UNPACKF2(lo, hi, ctx2[h]);
        sm[h * DPITCH + t] = (lo + hi) / lrun[h];   // ctx overlays ds buffer
    }
    __syncthreads();

    for (int c = t; c < CLIPD; c += 384) {
        const int h = c >> 6;
        const float* crow = sm + h * DPITCH;
        const float* wcol = Wv + c;
        float a0 = 0.f, a1 = 0.f, a2 = 0.f, a3 = 0.f;
        #pragma unroll 4
        for (int jx = 0; jx < DINOD; jx += 4) {
            a0 += crow[jx]     * wcol[(size_t)jx * CLIPD];
            a1 += crow[jx + 1] * wcol[(size_t)(jx + 1) * CLIPD];
            a2 += crow[jx + 2] * wcol[(size_t)(jx + 2) * CLIPD];
            a3 += crow[jx + 3] * wcol[(size_t)(jx + 3) * CLIPD];
        }
        outs[c] = a0 + a1 + a2 + a3 + bv[c];
    }
    __syncthreads();

    float s = 0.f, s2 = 0.f;
    for (int c = t; c < CLIPD; c += 384) { float v = outs[c]; s += v; s2 += v * v; }
    #pragma unroll
    for (int o = 16; o > 0; o >>= 1) {
        s  += __shfl_xor_sync(0xffffffffu, s, o);
        s2 += __shfl_xor_sync(0xffffffffu, s2, o);
    }
    if (l == 0) { red[w] = s; red2[w] = s2; }
    __syncthreads();
    if (t == 0) {
        float ss = 0.f, ss2 = 0.f;
        for (int i = 0; i < 12; ++i) { ss += red[i]; ss2 += red2[i]; }
        float mu  = ss / 512.f;
        float var = ss2 / 512.f - mu * mu;
        stat[0] = mu;
        stat[1] = rsqrtf(var + 1e-5f);
    }
    __syncthreads();
    float mu = stat[0], rs = stat[1];
    for (int c = t; c < CLIPD; c += 384)
        out[(size_t)b * CLIPD + c] = (outs[c] - mu) * rs * gamma[c] + beta[c];
}

// ---------------------------------------------------------------------------
extern "C" void kernel_launch(void* const* d_in, const int* in_sizes, int n_in,
                              void* d_out, int out_size) {
    const float* dino  = (const float*)d_in[0];
    const float* clip  = (const float*)d_in[1];
    const float* Wq    = (const float*)d_in[2];
    const float* bq    = (const float*)d_in[3];
    const float* Wk    = (const float*)d_in[4];
    // d_in[5] = bk: cancels in softmax (constant per (b,h))
    const float* Wv    = (const float*)d_in[6];
    const float* bv    = (const float*)d_in[7];
    const float* temp  = (const float*)d_in[8];
    const float* gamma = (const float*)d_in[9];
    const float* beta  = (const float*)d_in[10];
    float* out = (float*)d_out;
    (void)in_sizes; (void)n_in; (void)out_size;

    cudaFuncSetAttribute(k_main, cudaFuncAttributeMaxDynamicSharedMemorySize, SMEM_BYTES);

    k_prep<<<dim3(32, 8), 384>>>(clip, Wq, bq, Wk, temp);
    k_main<<<NB, 384, SMEM_BYTES>>>(dino, Wv, bv, gamma, beta, out);
}